// round 6
// baseline (speedup 1.0000x reference)
#include <cuda_runtime.h>

#define NE 2049   // E is NE x NE
#define NH 2048   // Hx cols / Hy rows
#define NW 2047   // Hx rows / Hy cols
#define CFLf 0.35f

#define KF0 (-11.0f/6.0f)
#define KF1 (3.0f)
#define KF2 (-1.5f)
#define KF3 (1.0f/3.0f)
#define KB0 (-1.0f/3.0f)
#define KB1 (1.5f)
#define KB2 (-3.0f)
#define KB3 (11.0f/6.0f)

#define IT 8          // amper i-tile
#define FIT 4         // faraday i-tile
#define A_INT_Y 254   // amper interior: i0 = 5 + 8*y, i in [5,2036]
#define A_BND_Y 30    // 17 row strips + 13 col strips (j in {0..4} u {2041..2048})
#define F_INT_Y 510   // faraday interior: i0 = 2 + 4*y, i in [2,2041]
#define F_BND_Y 16    // 8 row strips + 8 col strips (j in {0,1} u {2042..2047})

__device__ __forceinline__ void load_M(float beta, float delta, float gamma,
                                       float& a0, float& a1,
                                       float& m01, float& m11, float& m21) {
    a0  = -0.25f * beta + 0.1f * gamma;
    a1  =  0.25f * beta - 0.1f * gamma;
    m01 =  0.25f * beta + delta - 0.5f - 0.1f * gamma;
    m11 = -2.0f * delta;
    m21 = -0.25f * beta + delta + 0.5f + 0.1f * gamma;
}

// ===========================================================================
// Scalar point functions (verified) — boundary strips.
// ===========================================================================
__device__ void amper_point(int i, int j,
                            const float* __restrict__ Eb,
                            const float* __restrict__ Hxb,
                            const float* __restrict__ Hyb,
                            float a0, float a1, float m01, float m11, float m21,
                            float* __restrict__ Eob) {
    const bool ic = (i >= 2 && i <= NE - 3);
    const bool jc = (j >= 2 && j <= NE - 3);
    float s1 = 0.0f, s2 = 0.0f;

    if (ic && jc) {
        const float* r0 = Hyb + (size_t)(i - 2) * NW + (j - 2);
        const float* r1 = r0 + NW;
        const float* r2 = r1 + NW;
        const float* r3 = r2 + NW;
        s1 += a0  * r0[0] + a1  * r0[2]
            + m01 * r1[0] + m11 * r1[1] + m21 * r1[2]
            + a1  * r2[0] + a0  * r2[2]
            + a0  * r3[0] + a1  * r3[2];
        const float* x0 = Hxb + (size_t)(i - 2) * NH + (j - 2);
        const float* x1 = x0 + NH;
        const float* x2 = x1 + NH;
        s2 += a0 * x0[0] + m01 * x0[1] + a1 * x0[2] + a0 * x0[3]
            + m11 * x1[1]
            + a1 * x2[0] + m21 * x2[1] + a0 * x2[2] + a1 * x2[3];
    }
    if (i >= 1 && j <= NE - 6) {
        const float* r = Hyb + (size_t)(i - 1) * NW + j;
        s1 += KF0 * r[0] + KF1 * r[1] + KF2 * r[2] + KF3 * r[3];
    }
    if (i <= NE - 2 && j >= 5) {
        const float* r = Hyb + (size_t)i * NW + (j - 5);
        s1 += KB0 * r[0] + KB1 * r[1] + KB2 * r[2] + KB3 * r[3];
    }
    if (ic && (j == 1 || j == 2)) {
        const float* r = Hyb + (size_t)(i - 1) * NW + (j - 1);
        s1 += -r[0] + 3.0f * r[1] - 3.0f * r[2] + r[3];
    }
    if (ic && (j == NE - 3 || j == NE - 2)) {
        const float* r = Hyb + (size_t)i * NW + (j - 4);
        s1 += r[0] - 3.0f * r[1] + 3.0f * r[2] - r[3];
    }
    if (i <= NE - 6 && j >= 1) {
        const float* x = Hxb + (size_t)i * NH + (j - 1);
        s2 += KF0 * x[0] + KF1 * x[NH] + KF2 * x[2 * NH] + KF3 * x[3 * NH];
    }
    if (i >= 5 && j <= NE - 2) {
        const float* x = Hxb + (size_t)(i - 5) * NH + j;
        s2 += KB0 * x[0] + KB1 * x[NH] + KB2 * x[2 * NH] + KB3 * x[3 * NH];
    }
    if ((i == 1 || i == 2) && jc) {
        const float* x = Hxb + (size_t)(i - 1) * NH + (j - 1);
        s2 += -x[0] + 3.0f * x[NH] - 3.0f * x[2 * NH] + x[3 * NH];
    }
    if ((i == NE - 3 || i == NE - 2) && jc) {
        const float* x = Hxb + (size_t)(i - 4) * NH + j;
        s2 += x[0] - 3.0f * x[NH] + 3.0f * x[2 * NH] - x[3 * NH];
    }
    Eob[(size_t)i * NE + j] = Eb[(size_t)i * NE + j] + CFLf * (s1 - s2);
}

__device__ void faraday_point(int i, int j,
                              const float* __restrict__ Eb,
                              const float* __restrict__ Hxb,
                              const float* __restrict__ Hyb,
                              float a0, float a1, float m01, float m11, float m21,
                              float* __restrict__ Hxob,
                              float* __restrict__ Hyob) {
    if (i < NW && j < NH) {
        float s3 = 0.0f;
        if (j >= 1 && j <= NH - 2) {
            const float* e0 = Eb + (size_t)i * NE + (j - 1);
            const float* e1 = e0 + NE;
            const float* e2 = e1 + NE;
            s3 += a0 * e0[0] + m01 * e0[1] + a1 * e0[2] + a0 * e0[3]
                + m11 * e1[1]
                + a1 * e2[0] + m21 * e2[1] + a0 * e2[2] + a1 * e2[3];
        }
        if (i <= NH - 4) {
            const float* e = Eb + (size_t)(i + 1) * NE + j;
            s3 += -1.5f * e[0] + 2.0f * e[NE] - 0.5f * e[2 * NE];
        }
        if (i >= 2) {
            const float* e = Eb + (size_t)(i - 1) * NE + (j + 1);
            s3 += 0.5f * e[0] - 2.0f * e[NE] + 1.5f * e[2 * NE];
        }
        const size_t off = (size_t)i * NH + j;
        Hxob[off] = Hxb[off] - CFLf * s3;
    }
    if (i < NH && j < NW) {
        float s4 = 0.0f;
        if (i >= 1 && i <= NH - 2) {
            const float* e0 = Eb + (size_t)(i - 1) * NE + j;
            const float* e1 = e0 + NE;
            const float* e2 = e1 + NE;
            const float* e3 = e2 + NE;
            s4 += a0  * e0[0] + a1  * e0[2]
                + m01 * e1[0] + m11 * e1[1] + m21 * e1[2]
                + a1  * e2[0] + a0  * e2[2]
                + a0  * e3[0] + a1  * e3[2];
        }
        if (j <= NH - 4) {
            const float* e = Eb + (size_t)i * NE + (j + 1);
            s4 += -1.5f * e[0] + 2.0f * e[1] - 0.5f * e[2];
        }
        if (j >= 2) {
            const float* e = Eb + (size_t)(i + 1) * NE + (j - 1);
            s4 += 0.5f * e[0] - 2.0f * e[1] + 1.5f * e[2];
        }
        const size_t off = (size_t)i * NW + j;
        Hyob[off] = Hyb[off] + CFLf * s4;
    }
}

// ===========================================================================
// Fused amper: interior IT=8 x JT=4 register-tiled + boundary strips.
// ===========================================================================
__global__ __launch_bounds__(256)
void amper_kernel(const float* __restrict__ E,
                  const float* __restrict__ Hx,
                  const float* __restrict__ Hy,
                  const float* __restrict__ pb,
                  const float* __restrict__ pd,
                  const float* __restrict__ pg,
                  float* __restrict__ Eo) {
    const int b = blockIdx.z;
    float a0, a1, m01, m11, m21;
    load_M(*pb, *pd, *pg, a0, a1, m01, m11, m21);

    const float* Eb  = E  + (size_t)b * NE * NE;
    const float* Hxb = Hx + (size_t)b * NW * NH;
    const float* Hyb = Hy + (size_t)b * NH * NW;
    float* Eob = Eo + (size_t)b * NE * NE;

    if (blockIdx.y >= A_INT_Y) {
        const int y = blockIdx.y - A_INT_Y;
        if (y < 17) {
            const int i = (y < 5) ? y : 2037 + (y - 5);
            const int j = blockIdx.x * 256 + threadIdx.x;
            if (j >= NE) return;
            amper_point(i, j, Eb, Hxb, Hyb, a0, a1, m01, m11, m21, Eob);
        } else {
            const int c = y - 17;
            const int j = (c < 5) ? c : 2041 + (c - 5);
            const int i = 5 + blockIdx.x * 256 + threadIdx.x;
            if (i > 2036) return;
            amper_point(i, j, Eb, Hxb, Hyb, a0, a1, m01, m11, m21, Eob);
        }
        return;
    }

    // ---- interior: quads j0 = 5 + 4q, q in [0,508]; i0 = 5 + 8*y ----
    const int q = blockIdx.x * 256 + threadIdx.x;
    if (q > 508) return;
    const int j0 = 5 + 4 * q;
    const int i0 = 5 + blockIdx.y * IT;

    const float a1k  = a1 + KB3;
    const float m21k = m21 + KF0;

    float acc[IT][4];
#pragma unroll
    for (int k = 0; k < IT; k++)
#pragma unroll
        for (int c = 0; c < 4; c++) acc[k][c] = 0.0f;

    // ---- s1: Hy rows i0-2 .. i0+8, window cols j0-5 .. j0+6 ----
    {
        const float* hy = Hyb + (size_t)(i0 - 2) * NW + (j0 - 5);
#pragma unroll
        for (int rr = 0; rr < IT + 3; ++rr) {
            const bool uA = (rr <= IT - 1);
            const bool uB = (rr >= 1 && rr <= IT);
            const bool uC = (rr >= 2 && rr <= IT + 1);
            const bool uD = (rr >= 3);
            float v[12];
#pragma unroll
            for (int t = 0; t < 12; t++) v[t] = 0.0f;
            v[3] = hy[3]; v[4] = hy[4]; v[5] = hy[5];
            v[6] = hy[6]; v[7] = hy[7]; v[8] = hy[8];
            if (uC) { v[0] = hy[0]; v[1] = hy[1]; v[2] = hy[2]; }
            if (uB) { v[9] = hy[9]; v[10] = hy[10]; v[11] = hy[11]; }

            float t0 = a0 * v[3] + a1 * v[5];
            float t1 = a0 * v[4] + a1 * v[6];
            float t2 = a0 * v[5] + a1 * v[7];
            float t3 = a0 * v[6] + a1 * v[8];
            if (uA) { acc[rr][0] += t0; acc[rr][1] += t1;
                      acc[rr][2] += t2; acc[rr][3] += t3; }
            if (uB) {
#pragma unroll
                for (int c = 0; c < 4; c++)
                    acc[rr - 1][c] += m01 * v[c + 3] + m11 * v[c + 4] + m21k * v[c + 5]
                                    + KF1 * v[c + 6] + KF2 * v[c + 7] + KF3 * v[c + 8];
            }
            if (uC) {
#pragma unroll
                for (int c = 0; c < 4; c++)
                    acc[rr - 2][c] += KB0 * v[c] + KB1 * v[c + 1] + KB2 * v[c + 2]
                                    + a1k * v[c + 3] + a0 * v[c + 5];
            }
            if (uD) { acc[rr - 3][0] += t0; acc[rr - 3][1] += t1;
                      acc[rr - 3][2] += t2; acc[rr - 3][3] += t3; }
            hy += NW;
        }
    }

    // ---- s2 (subtract): Hx rows i0-5 .. i0+10, window cols j0-2 .. j0+4 ----
    {
        const float* hx = Hxb + (size_t)(i0 - 5) * NH + (j0 - 2);
#pragma unroll
        for (int rr = 0; rr < IT + 8; ++rr) {
            const bool vK0 = (rr <= IT - 1);
            const bool vK1 = (rr >= 1 && rr <= IT);
            const bool vK2 = (rr >= 2 && rr <= IT + 1);
            const bool vA  = (rr >= 3 && rr <= IT + 2);
            const bool vB  = (rr >= 4 && rr <= IT + 3);
            const bool vC  = (rr >= 5 && rr <= IT + 4);
            const bool vD  = (rr >= 6 && rr <= IT + 5);
            const bool vE  = (rr >= 7 && rr <= IT + 6);
            const bool vF  = (rr >= 8);
            const bool needAC = (vA | vC);
            float w[7];
#pragma unroll
            for (int t = 0; t < 7; t++) w[t] = 0.0f;
            w[2] = hx[2]; w[3] = hx[3]; w[4] = hx[4];
            if (rr <= IT + 4) w[5] = hx[5];
            if (rr >= 3)      w[1] = hx[1];
            if (needAC) { w[0] = hx[0]; w[6] = hx[6]; }

            if (vK0) {
#pragma unroll
                for (int c = 0; c < 4; c++) acc[rr][c] -= KB0 * w[c + 2];
            }
            if (vK1) {
#pragma unroll
                for (int c = 0; c < 4; c++) acc[rr - 1][c] -= KB1 * w[c + 2];
            }
            if (vK2) {
#pragma unroll
                for (int c = 0; c < 4; c++) acc[rr - 2][c] -= KB2 * w[c + 2];
            }
            if (vA) {
#pragma unroll
                for (int c = 0; c < 4; c++)
                    acc[rr - 3][c] -= a0 * w[c] + m01 * w[c + 1] + a1k * w[c + 2] + a0 * w[c + 3];
            }
            if (vB) {
#pragma unroll
                for (int c = 0; c < 4; c++) acc[rr - 4][c] -= m11 * w[c + 1];
            }
            if (vC) {
#pragma unroll
                for (int c = 0; c < 4; c++)
                    acc[rr - 5][c] -= a1 * w[c] + m21k * w[c + 1] + a0 * w[c + 2] + a1 * w[c + 3];
            }
            if (vD) {
#pragma unroll
                for (int c = 0; c < 4; c++) acc[rr - 6][c] -= KF1 * w[c + 1];
            }
            if (vE) {
#pragma unroll
                for (int c = 0; c < 4; c++) acc[rr - 7][c] -= KF2 * w[c + 1];
            }
            if (vF) {
#pragma unroll
                for (int c = 0; c < 4; c++) acc[rr - 8][c] -= KF3 * w[c + 1];
            }
            hx += NH;
        }
    }

    const size_t off = (size_t)i0 * NE + j0;
#pragma unroll
    for (int k = 0; k < IT; k++) {
#pragma unroll
        for (int c = 0; c < 4; c++) {
            const size_t o = off + (size_t)k * NE + c;
            Eob[o] = Eb[o] + CFLf * acc[k][c];
        }
    }
}

// ===========================================================================
// Fused faraday (Hx+Hy): interior FIT=4 x JT=4 register-tiled + boundary.
// ===========================================================================
__global__ __launch_bounds__(256)
void faraday_kernel(const float* __restrict__ E,
                    const float* __restrict__ Hx,
                    const float* __restrict__ Hy,
                    const float* __restrict__ pb,
                    const float* __restrict__ pd,
                    const float* __restrict__ pg,
                    float* __restrict__ Hxo,
                    float* __restrict__ Hyo) {
    const int b = blockIdx.z;
    float a0, a1, m01, m11, m21;
    load_M(*pb, *pd, *pg, a0, a1, m01, m11, m21);

    const float* Eb  = E  + (size_t)b * NE * NE;
    const float* Hxb = Hx + (size_t)b * NW * NH;
    const float* Hyb = Hy + (size_t)b * NH * NW;
    float* Hxob = Hxo + (size_t)b * NW * NH;
    float* Hyob = Hyo + (size_t)b * NH * NW;

    if (blockIdx.y >= F_INT_Y) {
        const int y = blockIdx.y - F_INT_Y;
        if (y < 8) {
            const int i = (y < 2) ? y : 2042 + (y - 2);
            const int j = blockIdx.x * 256 + threadIdx.x;
            if (j >= NH) return;
            faraday_point(i, j, Eb, Hxb, Hyb, a0, a1, m01, m11, m21, Hxob, Hyob);
        } else {
            const int c = y - 8;
            const int j = (c < 2) ? c : 2042 + (c - 2);
            const int i = 2 + blockIdx.x * 256 + threadIdx.x;
            if (i > 2041) return;
            faraday_point(i, j, Eb, Hxb, Hyb, a0, a1, m01, m11, m21, Hxob, Hyob);
        }
        return;
    }

    // ---- interior: quads j0 = 2 + 4q, q in [0,509]; i0 = 2 + 4*y ----
    const int q = blockIdx.x * 256 + threadIdx.x;
    if (q > 509) return;
    const int j0 = 2 + 4 * q;
    const int i0 = 2 + blockIdx.y * FIT;

    const float m11b = m11 - 1.5f;
    const float m21b = m21 + 2.0f;
    const float a1m2 = a1 - 2.0f;

    float sx[FIT][4], sy[FIT][4];
#pragma unroll
    for (int k = 0; k < FIT; k++)
#pragma unroll
        for (int c = 0; c < 4; c++) { sx[k][c] = 0.0f; sy[k][c] = 0.0f; }

    const float* ep = Eb + (size_t)(i0 - 1) * NE + (j0 - 1);
#pragma unroll
    for (int rr = 0; rr < FIT + 4; ++rr) {
        const bool w0 = (rr <= FIT - 1);
        const bool w1 = (rr >= 1 && rr <= FIT);
        const bool w2 = (rr >= 2 && rr <= FIT + 1);
        const bool w3 = (rr >= 3 && rr <= FIT + 2);
        const bool w4 = (rr >= 4);
        float v[8];
#pragma unroll
        for (int t = 0; t < 8; t++) v[t] = 0.0f;
        v[1] = ep[1]; v[2] = ep[2]; v[3] = ep[3]; v[4] = ep[4];
        if (w1 | w2 | w3) v[0] = ep[0];
        if (w0 | w1 | w2 | w3) { v[5] = ep[5]; v[6] = ep[6]; }
        if (w1) v[7] = ep[7];

        float ty0 = a0 * v[1] + a1 * v[3];
        float ty1 = a0 * v[2] + a1 * v[4];
        float ty2 = a0 * v[3] + a1 * v[5];
        float ty3 = a0 * v[4] + a1 * v[6];

        if (w0) {
#pragma unroll
            for (int c = 0; c < 4; c++) sx[rr][c] += 0.5f * v[c + 2];
            sy[rr][0] += ty0; sy[rr][1] += ty1; sy[rr][2] += ty2; sy[rr][3] += ty3;
        }
        if (w1) {
#pragma unroll
            for (int c = 0; c < 4; c++) {
                sx[rr - 1][c] += a0 * v[c] + m01 * v[c + 1] + a1m2 * v[c + 2] + a0 * v[c + 3];
                sy[rr - 1][c] += m01 * v[c + 1] + m11b * v[c + 2] + m21b * v[c + 3] - 0.5f * v[c + 4];
            }
        }
        if (w2) {
#pragma unroll
            for (int c = 0; c < 4; c++) {
                sx[rr - 2][c] += m11b * v[c + 1] + 1.5f * v[c + 2];
                sy[rr - 2][c] += 0.5f * v[c] + a1m2 * v[c + 1] + 1.5f * v[c + 2] + a0 * v[c + 3];
            }
        }
        if (w3) {
#pragma unroll
            for (int c = 0; c < 4; c++)
                sx[rr - 3][c] += a1 * v[c] + m21b * v[c + 1] + a0 * v[c + 2] + a1 * v[c + 3];
            sy[rr - 3][0] += ty0; sy[rr - 3][1] += ty1;
            sy[rr - 3][2] += ty2; sy[rr - 3][3] += ty3;
        }
        if (w4) {
#pragma unroll
            for (int c = 0; c < 4; c++) sx[rr - 4][c] -= 0.5f * v[c + 1];
        }
        ep += NE;
    }

    const size_t offx = (size_t)i0 * NH + j0;
    const size_t offy = (size_t)i0 * NW + j0;
#pragma unroll
    for (int k = 0; k < FIT; k++) {
#pragma unroll
        for (int c = 0; c < 4; c++) {
            const size_t ox = offx + (size_t)k * NH + c;
            const size_t oy = offy + (size_t)k * NW + c;
            Hxob[ox] = Hxb[ox] - CFLf * sx[k][c];
            Hyob[oy] = Hyb[oy] + CFLf * sy[k][c];
        }
    }
}

// ===========================================================================
extern "C" void kernel_launch(void* const* d_in, const int* in_sizes, int n_in,
                              void* d_out, int out_size) {
    const float* E0  = (const float*)d_in[0];
    const float* Hx0 = (const float*)d_in[1];
    const float* Hy0 = (const float*)d_in[2];
    const float* pb  = (const float*)d_in[3];
    const float* pd  = (const float*)d_in[4];
    const float* pg  = (const float*)d_in[5];

    const int B = in_sizes[0] / (NE * NE);

    const size_t nE  = (size_t)B * NE * NE;
    const size_t nHx = (size_t)B * NW * NH;
    const size_t nHy = (size_t)B * NH * NW;

    float* out = (float*)d_out;
    float* E2  = out;
    float* Hx2 = E2 + nE;
    float* Hy2 = Hx2 + nHx;
    float* E3  = Hy2 + nHy;
    float* Hx3 = E3 + nE;
    float* Hy3 = Hx3 + nHx;
    float* E4  = Hy3 + nHy;
    float* Hx4 = E4 + nE;
    float* Hy4 = Hx4 + nHx;

    dim3 blk(256);
    dim3 gA(9, A_INT_Y + A_BND_Y, B);  // x=9 for 2049-wide boundary rows
    dim3 gF(8, F_INT_Y + F_BND_Y, B);  // x=8 for 2048-wide boundary rows

    const float* Ein  = E0;
    const float* Hxin = Hx0;
    const float* Hyin = Hy0;
    float* Eouts[3]  = {E2, E3, E4};
    float* Hxouts[3] = {Hx2, Hx3, Hx4};
    float* Hyouts[3] = {Hy2, Hy3, Hy4};

    for (int s = 0; s < 3; s++) {
        amper_kernel<<<gA, blk>>>(Ein, Hxin, Hyin, pb, pd, pg, Eouts[s]);
        faraday_kernel<<<gF, blk>>>(Eouts[s], Hxin, Hyin, pb, pd, pg,
                                    Hxouts[s], Hyouts[s]);
        Ein = Eouts[s]; Hxin = Hxouts[s]; Hyin = Hyouts[s];
    }
}